// round 5
// baseline (speedup 1.0000x reference)
#include <cuda_runtime.h>
#include <cstdint>

// Shapes (fixed): B=4, N=8, M=64, F=128, D=128
#define BN_TOT 32
#define M_DIM  64
#define F_DIM  128
#define D_DIM  128
#define EPS_LN 1e-5f

// Scratch: P (which=0), Q (which=1), R (which=2), each [32][64][128] fp32.
__device__ float g_scratch[3 * BN_TOT * M_DIM * F_DIM];
// Precomputed W2 bf16 slabs (hi at 0, lo at 32768), swizzled layout, 64 KB.
__device__ __align__(16) unsigned char g_w2[65536];

// ---------------------------------------------------------------------------
// Stage 1 (unchanged): per (b,n) compute P/Q/R linear projections.
// ---------------------------------------------------------------------------
__global__ void hoe_stage1(const float* __restrict__ x,
                           const float* __restrict__ W1,
                           const float* __restrict__ b1) {
    extern __shared__ float sm[];
    float* xs     = sm;                     // 64*128
    float* wt     = xs + M_DIM * F_DIM;     // 128*129
    float* mean_s = wt + F_DIM * 129;       // 128
    float* mv_s   = mean_s + F_DIM;         // 128

    const int bn    = blockIdx.x;
    const int which = blockIdx.y;           // 0:P 1:Q 2:R
    const int tid   = threadIdx.x;

    const float* xb = x + bn * (M_DIM * F_DIM);
    for (int idx = tid; idx < M_DIM * F_DIM; idx += 256) xs[idx] = xb[idx];
    __syncthreads();

    if (tid < F_DIM) {
        float s = 0.f;
        #pragma unroll 8
        for (int i2 = 0; i2 < M_DIM; i2++) s += xs[i2 * F_DIM + tid];
        mean_s[tid] = s * (1.0f / M_DIM);
    }

    const int off_main = (which == 0) ? 128 : (which == 1) ? 256 : 0;
    __syncthreads();
    for (int idx = tid; idx < F_DIM * F_DIM; idx += 256) {
        const int f = idx >> 7, k = idx & 127;
        wt[k * 129 + f] = W1[f * 640 + off_main + k];
    }
    __syncthreads();

    const int ty = tid >> 5, tx = tid & 31;
    float acc[8][4];
    #pragma unroll
    for (int ii = 0; ii < 8; ii++)
        #pragma unroll
        for (int ff = 0; ff < 4; ff++) acc[ii][ff] = 0.f;

    for (int k = 0; k < F_DIM; k += 4) {
        float4 xv[8];
        #pragma unroll
        for (int ii = 0; ii < 8; ii++)
            xv[ii] = *(const float4*)&xs[(ty * 8 + ii) * F_DIM + k];
        #pragma unroll
        for (int kk = 0; kk < 4; kk++) {
            const float w0 = wt[(k + kk) * 129 + tx];
            const float w1 = wt[(k + kk) * 129 + tx + 32];
            const float w2 = wt[(k + kk) * 129 + tx + 64];
            const float w3 = wt[(k + kk) * 129 + tx + 96];
            #pragma unroll
            for (int ii = 0; ii < 8; ii++) {
                const float xk = (kk == 0) ? xv[ii].x : (kk == 1) ? xv[ii].y
                               : (kk == 2) ? xv[ii].z : xv[ii].w;
                acc[ii][0] = fmaf(xk, w0, acc[ii][0]);
                acc[ii][1] = fmaf(xk, w1, acc[ii][1]);
                acc[ii][2] = fmaf(xk, w2, acc[ii][2]);
                acc[ii][3] = fmaf(xk, w3, acc[ii][3]);
            }
        }
    }

    if (which != 1) {
        const int off2 = (which == 0) ? 512 : 384;
        __syncthreads();
        for (int idx = tid; idx < F_DIM * F_DIM; idx += 256) {
            const int f = idx >> 7, k = idx & 127;
            wt[k * 129 + f] = W1[f * 640 + off2 + k];
        }
        __syncthreads();
        if (tid < F_DIM) {
            float s = 0.f;
            #pragma unroll 8
            for (int k = 0; k < F_DIM; k++) s = fmaf(mean_s[k], wt[k * 129 + tid], s);
            mv_s[tid] = s;
        }
        __syncthreads();
    }

    float* outp = g_scratch + which * (BN_TOT * M_DIM * F_DIM) + bn * (M_DIM * F_DIM);
    #pragma unroll
    for (int ff = 0; ff < 4; ff++) {
        const int f = tx + 32 * ff;
        float extra = 0.f;
        if (which != 1) extra += mv_s[f];
        if (which == 0) extra += b1[f];
        #pragma unroll
        for (int ii = 0; ii < 8; ii++)
            outp[(ty * 8 + ii) * F_DIM + f] = acc[ii][ff] + extra;
    }
}

// ---------------------------------------------------------------------------
// Helpers
// ---------------------------------------------------------------------------
static __device__ __forceinline__ uint32_t cvta_smem(const void* p) {
    uint32_t a;
    asm("{ .reg .u64 t; cvta.to.shared.u64 t, %1; cvt.u32.u64 %0, t; }"
        : "=r"(a) : "l"(p));
    return a;
}
// pack bf16(lo), bf16(hi): lo in low 16 bits
static __device__ __forceinline__ uint32_t packbf(float lo, float hi) {
    uint32_t r;
    asm("cvt.rn.bf16x2.f32 %0, %1, %2;" : "=r"(r) : "f"(hi), "f"(lo));
    return r;
}
// swizzled byte offset within a slab: row, kbyte in [0,256)
static __device__ __forceinline__ uint32_t swz(uint32_t row, uint32_t kbyte) {
    return row * 256u + ((((kbyte >> 4) ^ (row & 7u)) << 4) | (kbyte & 15u));
}
static __device__ __forceinline__ void ldsm4(uint32_t* r, uint32_t addr) {
    asm volatile("ldmatrix.sync.aligned.m8n8.x4.shared.b16 {%0,%1,%2,%3}, [%4];"
                 : "=r"(r[0]), "=r"(r[1]), "=r"(r[2]), "=r"(r[3]) : "r"(addr));
}
static __device__ __forceinline__ void mma16816(float* c, const uint32_t* a,
                                                uint32_t b0, uint32_t b1) {
    asm volatile(
        "mma.sync.aligned.m16n8k16.row.col.f32.bf16.bf16.f32 "
        "{%0,%1,%2,%3}, {%4,%5,%6,%7}, {%8,%9}, {%0,%1,%2,%3};"
        : "+f"(c[0]), "+f"(c[1]), "+f"(c[2]), "+f"(c[3])
        : "r"(a[0]), "r"(a[1]), "r"(a[2]), "r"(a[3]), "r"(b0), "r"(b1));
}
static __device__ __forceinline__ void cp_async16(uint32_t dst, const void* gp) {
    uint64_t g;
    asm("cvta.to.global.u64 %0, %1;" : "=l"(g) : "l"(gp));
    asm volatile("cp.async.cg.shared.global [%0], [%1], 16;"
                 :: "r"(dst), "l"(g) : "memory");
}

// ---------------------------------------------------------------------------
// W2 prep: convert W2 -> bf16 hi/lo into g_w2 in swizzled slab layout. Once.
// ---------------------------------------------------------------------------
__global__ void hoe_w2prep(const float* __restrict__ W2) {
    const int idx = blockIdx.x * 256 + threadIdx.x;   // < 4096
    const int d  = idx >> 5;
    const int cw = idx & 31;
    const float4 v = __ldg((const float4*)(W2 + d * 128 + cw * 4));
    const uint32_t hiA = packbf(v.x, v.y);
    const uint32_t hiB = packbf(v.z, v.w);
    const float r0 = v.x - __uint_as_float(hiA << 16);
    const float r1 = v.y - __uint_as_float(hiA & 0xffff0000u);
    const float r2 = v.z - __uint_as_float(hiB << 16);
    const float r3 = v.w - __uint_as_float(hiB & 0xffff0000u);
    const uint32_t loA = packbf(r0, r1);
    const uint32_t loB = packbf(r2, r3);
    const uint32_t off = swz((uint32_t)d, (uint32_t)cw * 8u);
    *(uint2*)(g_w2 + off)         = make_uint2(hiA, hiB);
    *(uint2*)(g_w2 + 32768 + off) = make_uint2(loA, loB);
}

// ---------------------------------------------------------------------------
// Stage 2: one block per (bn, i). M=64 (j), N=128 (d), K=128 (f).
// 3-term bf16 split, one K=384 mainloop. 2 CTAs/SM.
// ---------------------------------------------------------------------------
#define AHI 0
#define ALO 16384
#define BHI 32768
#define BLO 65536
#define VECO 98304
#define SMEM2_BYTES 101376

__global__ void __launch_bounds__(256, 2)
hoe_stage2_mma(const float* __restrict__ gamma,
               const float* __restrict__ beta,
               const float* __restrict__ bias_p,
               const float* __restrict__ b2,
               float* __restrict__ out) {
    extern __shared__ char smem[];
    float* Pv  = (float*)(smem + VECO);      // 128
    float* Rv  = Pv + 128;
    float* gv  = Rv + 128;
    float* bv  = gv + 128;
    float* bpv = bv + 128;
    float* b2v = bpv + 128;

    const uint32_t sbase = cvta_smem(smem);
    const int tid  = threadIdx.x;
    const int lane = tid & 31;
    const int wid  = tid >> 5;
    const int bid  = blockIdx.x;
    const int bn   = bid >> 6;
    const int i    = bid & 63;

    // Per-block vectors (warp-parallel LDG -> STS)
    if (tid < 128) {
        const int pofs = bn * (M_DIM * F_DIM) + i * F_DIM;
        Pv[tid]  = g_scratch[0 * (BN_TOT * M_DIM * F_DIM) + pofs + tid];
        Rv[tid]  = g_scratch[2 * (BN_TOT * M_DIM * F_DIM) + pofs + tid];
        gv[tid]  = gamma[tid];
        bv[tid]  = beta[tid];
        bpv[tid] = bias_p[tid];
        b2v[tid] = b2[tid];
    }

    // Kick off B-slab copy (64 KB raw, already swizzled+converted) via cp.async
    #pragma unroll
    for (int it = 0; it < 16; it++) {
        const int idx = it * 256 + tid;
        cp_async16(sbase + BHI + idx * 16, g_w2 + idx * 16);
    }
    asm volatile("cp.async.commit_group;" ::: "memory");

    // Prefetch Q rows for this warp (8 rows, batched LDG.128)
    const float* Qg = g_scratch + 1 * (BN_TOT * M_DIM * F_DIM) + bn * (M_DIM * F_DIM);
    float4 q4[8];
    #pragma unroll
    for (int r = 0; r < 8; r++)
        q4[r] = __ldg((const float4*)(Qg + (wid * 8 + r) * 128 + lane * 4));

    __syncthreads();   // vecs visible

    // LayerNorm + ReLU + diag bias + bf16 split -> A slabs. 8 rows/warp.
    const int f4 = lane * 4;
    const float pv0 = Pv[f4], pv1 = Pv[f4 + 1], pv2 = Pv[f4 + 2], pv3 = Pv[f4 + 3];
    #pragma unroll
    for (int r = 0; r < 8; r++) {
        const int m = wid * 8 + r;          // j == m
        const bool diag = (m == i);

        float v0 = q4[r].x + pv0;
        float v1 = q4[r].y + pv1;
        float v2 = q4[r].z + pv2;
        float v3 = q4[r].w + pv3;
        if (diag) {
            v0 += Rv[f4 + 0]; v1 += Rv[f4 + 1]; v2 += Rv[f4 + 2]; v3 += Rv[f4 + 3];
        }
        float s = v0 + v1 + v2 + v3;
        #pragma unroll
        for (int o = 16; o > 0; o >>= 1) s += __shfl_xor_sync(0xffffffffu, s, o);
        const float mu = s * (1.0f / F_DIM);
        v0 -= mu; v1 -= mu; v2 -= mu; v3 -= mu;
        float ss = v0 * v0 + v1 * v1 + v2 * v2 + v3 * v3;
        #pragma unroll
        for (int o = 16; o > 0; o >>= 1) ss += __shfl_xor_sync(0xffffffffu, ss, o);
        const float rstd = rsqrtf(ss * (1.0f / F_DIM) + EPS_LN);

        float h0 = fmaxf(fmaf(v0 * rstd, gv[f4 + 0], bv[f4 + 0]), 0.f);
        float h1 = fmaxf(fmaf(v1 * rstd, gv[f4 + 1], bv[f4 + 1]), 0.f);
        float h2 = fmaxf(fmaf(v2 * rstd, gv[f4 + 2], bv[f4 + 2]), 0.f);
        float h3 = fmaxf(fmaf(v3 * rstd, gv[f4 + 3], bv[f4 + 3]), 0.f);
        if (diag) { h0 += bpv[f4 + 0]; h1 += bpv[f4 + 1]; h2 += bpv[f4 + 2]; h3 += bpv[f4 + 3]; }

        const uint32_t hiA = packbf(h0, h1);
        const uint32_t hiB = packbf(h2, h3);
        const float r0 = h0 - __uint_as_float(hiA << 16);
        const float r1 = h1 - __uint_as_float(hiA & 0xffff0000u);
        const float r2 = h2 - __uint_as_float(hiB << 16);
        const float r3 = h3 - __uint_as_float(hiB & 0xffff0000u);
        const uint32_t loA = packbf(r0, r1);
        const uint32_t loB = packbf(r2, r3);
        const uint32_t off = swz((uint32_t)m, (uint32_t)lane * 8u);
        *(uint2*)(smem + AHI + off) = make_uint2(hiA, hiB);
        *(uint2*)(smem + ALO + off) = make_uint2(loA, loB);
    }
    asm volatile("cp.async.wait_group 0;" ::: "memory");
    __syncthreads();

    // --- MMA mainloop. Warp grid 2x4: warp tile 32(M) x 32(N). ---
    const int warpM = wid >> 2;               // 0..1
    const int warpN = wid & 3;                // 0..3
    const int q  = lane >> 3;
    const int lr = lane & 7;

    const int rowA  = lr + ((q & 1) << 3);
    const int cselA = q >> 1;
    uint32_t rowOffA[2];
    #pragma unroll
    for (int mt = 0; mt < 2; mt++)
        rowOffA[mt] = (uint32_t)(warpM * 32 + mt * 16 + rowA) * 256u;

    const int rowB  = lr + ((q >> 1) << 3);
    const int cselB = q & 1;
    uint32_t rowOffB[2];
    #pragma unroll
    for (int np = 0; np < 2; np++)
        rowOffB[np] = (uint32_t)(warpN * 32 + np * 16 + rowB) * 256u;

    float acc[2][4][4];
    #pragma unroll
    for (int mt = 0; mt < 2; mt++)
        #pragma unroll
        for (int nt = 0; nt < 4; nt++)
            #pragma unroll
            for (int e = 0; e < 4; e++) acc[mt][nt][e] = 0.f;

    const uint32_t slabsA[3] = { sbase + AHI, sbase + ALO, sbase + AHI };
    const uint32_t slabsB[3] = { sbase + BHI, sbase + BHI, sbase + BLO };

    #pragma unroll
    for (int p = 0; p < 3; p++) {
        const uint32_t sa = slabsA[p];
        const uint32_t sb = slabsB[p];
        #pragma unroll
        for (int kk = 0; kk < 8; kk++) {
            const uint32_t kxA = (uint32_t)(((kk << 1) + cselA) ^ lr) << 4;
            const uint32_t kxB = (uint32_t)(((kk << 1) + cselB) ^ lr) << 4;
            uint32_t af[2][4], bf[2][4];
            #pragma unroll
            for (int mt = 0; mt < 2; mt++) ldsm4(af[mt], sa + rowOffA[mt] + kxA);
            #pragma unroll
            for (int np = 0; np < 2; np++) ldsm4(bf[np], sb + rowOffB[np] + kxB);
            #pragma unroll
            for (int mt = 0; mt < 2; mt++) {
                #pragma unroll
                for (int nt = 0; nt < 4; nt++) {
                    const int np = nt >> 1;
                    const int hb = (nt & 1) << 1;
                    mma16816(acc[mt][nt], af[mt], bf[np][hb], bf[np][hb + 1]);
                }
            }
        }
    }

    // Epilogue: add b2, store fp32 directly
    float* oblk = out + ((size_t)(bn * 64 + i) * 64) * 128;
    #pragma unroll
    for (int mt = 0; mt < 2; mt++) {
        #pragma unroll
        for (int half = 0; half < 2; half++) {
            const int m = warpM * 32 + mt * 16 + (lane >> 2) + half * 8;
            float* orow = oblk + (size_t)m * 128;
            #pragma unroll
            for (int nt = 0; nt < 4; nt++) {
                const int n = warpN * 32 + nt * 8 + (lane & 3) * 2;
                float2 v;
                v.x = acc[mt][nt][half * 2 + 0] + b2v[n];
                v.y = acc[mt][nt][half * 2 + 1] + b2v[n + 1];
                *(float2*)(orow + n) = v;
            }
        }
    }
}

// ---------------------------------------------------------------------------
extern "C" void kernel_launch(void* const* d_in, const int* in_sizes, int n_in,
                              void* d_out, int out_size) {
    const float* x      = (const float*)d_in[0];
    const float* W1     = (const float*)d_in[1];
    const float* b1     = (const float*)d_in[2];
    const float* gamma  = (const float*)d_in[3];
    const float* beta   = (const float*)d_in[4];
    const float* bias_p = (const float*)d_in[5];
    const float* W2     = (const float*)d_in[6];
    const float* b2     = (const float*)d_in[7];
    float* out          = (float*)d_out;

    const int smem1 = (M_DIM * F_DIM + F_DIM * 129 + 2 * F_DIM) * (int)sizeof(float);
    cudaFuncSetAttribute(hoe_stage1, cudaFuncAttributeMaxDynamicSharedMemorySize, smem1);
    cudaFuncSetAttribute(hoe_stage2_mma, cudaFuncAttributeMaxDynamicSharedMemorySize, SMEM2_BYTES);

    dim3 grid1(BN_TOT, 3);
    hoe_stage1<<<grid1, 256, smem1>>>(x, W1, b1);
    hoe_w2prep<<<16, 256>>>(W2);
    hoe_stage2_mma<<<BN_TOT * M_DIM, 256, SMEM2_BYTES>>>(gamma, beta, bias_p, b2, out);
}

// round 6
// speedup vs baseline: 1.6721x; 1.6721x over previous
#include <cuda_runtime.h>
#include <cstdint>

// Shapes (fixed): B=4, N=8, M=64, F=128, D=128
#define BN_TOT 32
#define M_DIM  64
#define F_DIM  128
#define D_DIM  128
#define EPS_LN 1e-5f

// C scratch: [bn][chunk0..4][64 rows][128] fp32 (chunks 3,4 not stored).
__device__ float g_C[BN_TOT * 5 * M_DIM * F_DIM];
// colmeans: [bn][0:R-term (chunk3), 1:P-term (chunk4)][128]
__device__ float g_means[BN_TOT * 2 * F_DIM];
// bf16 hi/lo swizzled slabs: [mat 0..5][hi=0,lo=1][32768 B]; mat 0..4 = W1 chunks, 5 = W2.
__device__ __align__(16) unsigned char g_wsl[6 * 2 * 32768];

// ---------------------------------------------------------------------------
// Helpers
// ---------------------------------------------------------------------------
static __device__ __forceinline__ uint32_t cvta_smem(const void* p) {
    uint32_t a;
    asm("{ .reg .u64 t; cvta.to.shared.u64 t, %1; cvt.u32.u64 %0, t; }"
        : "=r"(a) : "l"(p));
    return a;
}
// pack bf16(lo), bf16(hi): lo in low 16 bits
static __device__ __forceinline__ uint32_t packbf(float lo, float hi) {
    uint32_t r;
    asm("cvt.rn.bf16x2.f32 %0, %1, %2;" : "=r"(r) : "f"(hi), "f"(lo));
    return r;
}
// swizzled byte offset within a slab: row, kbyte in [0,256)
static __device__ __forceinline__ uint32_t swz(uint32_t row, uint32_t kbyte) {
    return row * 256u + ((((kbyte >> 4) ^ (row & 7u)) << 4) | (kbyte & 15u));
}
static __device__ __forceinline__ void ldsm4(uint32_t* r, uint32_t addr) {
    asm volatile("ldmatrix.sync.aligned.m8n8.x4.shared.b16 {%0,%1,%2,%3}, [%4];"
                 : "=r"(r[0]), "=r"(r[1]), "=r"(r[2]), "=r"(r[3]) : "r"(addr));
}
static __device__ __forceinline__ void mma16816(float* c, const uint32_t* a,
                                                uint32_t b0, uint32_t b1) {
    asm volatile(
        "mma.sync.aligned.m16n8k16.row.col.f32.bf16.bf16.f32 "
        "{%0,%1,%2,%3}, {%4,%5,%6,%7}, {%8,%9}, {%0,%1,%2,%3};"
        : "+f"(c[0]), "+f"(c[1]), "+f"(c[2]), "+f"(c[3])
        : "r"(a[0]), "r"(a[1]), "r"(a[2]), "r"(a[3]), "r"(b0), "r"(b1));
}
static __device__ __forceinline__ void cp_async16(uint32_t dst, const void* gp) {
    uint64_t g;
    asm("cvta.to.global.u64 %0, %1;" : "=l"(g) : "l"(gp));
    asm volatile("cp.async.cg.shared.global [%0], [%1], 16;"
                 :: "r"(dst), "l"(g) : "memory");
}
// split a float4 into bf16 hi/lo packed pairs
static __device__ __forceinline__ void split4(const float4& v, uint2& hi, uint2& lo) {
    const uint32_t hiA = packbf(v.x, v.y);
    const uint32_t hiB = packbf(v.z, v.w);
    const float r0 = v.x - __uint_as_float(hiA << 16);
    const float r1 = v.y - __uint_as_float(hiA & 0xffff0000u);
    const float r2 = v.z - __uint_as_float(hiB << 16);
    const float r3 = v.w - __uint_as_float(hiB & 0xffff0000u);
    hi = make_uint2(hiA, hiB);
    lo = make_uint2(packbf(r0, r1), packbf(r2, r3));
}

// ---------------------------------------------------------------------------
// Prep: convert W1 (5 chunks, B-layout rows=f_out, k=f_in) + W2 to bf16 slabs.
// grid 96 x 256 = 24576 threads; one float4 each.
// ---------------------------------------------------------------------------
__global__ void hoe_prep(const float* __restrict__ W1, const float* __restrict__ W2) {
    const int idx = blockIdx.x * 256 + threadIdx.x;   // < 24576
    const int mat = idx >> 12;                        // 0..5
    const int rem = idx & 4095;
    const int r   = rem >> 5;                          // row 0..127
    const int cw  = rem & 31;                          // float4 index in row
    const float* src = (mat < 5) ? (W1 + r * 640 + mat * 128 + cw * 4)
                                 : (W2 + r * 128 + cw * 4);
    const float4 v = __ldg((const float4*)src);
    uint2 hi, lo;
    split4(v, hi, lo);
    const uint32_t off = swz((uint32_t)r, (uint32_t)cw * 8u);
    *(uint2*)(g_wsl + (mat * 2 + 0) * 32768 + off) = hi;
    *(uint2*)(g_wsl + (mat * 2 + 1) * 32768 + off) = lo;
}

// ---------------------------------------------------------------------------
// Stage 1 (MMA): block (bn, chunk). C_chunk = x(64x128) . W1chunk^T (128x128).
// chunks 3,4: emit colmean only (the mean-row projections).
// ---------------------------------------------------------------------------
#define S1_AHI 0
#define S1_ALO 16384
#define S1_BHI 32768
#define S1_BLO 65536
#define S1_CM  98304
#define SMEM1_BYTES 98816

__global__ void __launch_bounds__(256, 2)
hoe_stage1mm(const float* __restrict__ x) {
    extern __shared__ char smem[];
    float* cm = (float*)(smem + S1_CM);
    const uint32_t sbase = cvta_smem(smem);
    const int tid  = threadIdx.x;
    const int lane = tid & 31;
    const int wid  = tid >> 5;
    const int bn    = blockIdx.x;
    const int chunk = blockIdx.y;

    if (tid < 128) cm[tid] = 0.f;

    // B slabs: hi+lo are contiguous 64 KB in g_wsl
    const unsigned char* bsrc = g_wsl + (chunk * 2) * 32768;
    #pragma unroll
    for (int it = 0; it < 16; it++) {
        const int idx = it * 256 + tid;
        cp_async16(sbase + S1_BHI + idx * 16, bsrc + idx * 16);
    }
    asm volatile("cp.async.commit_group;" ::: "memory");

    // A slabs: convert x tile (row-major, element e = row*32+cw float4s)
    const float4* xb = (const float4*)(x + bn * (M_DIM * F_DIM));
    #pragma unroll
    for (int it = 0; it < 8; it++) {
        const int e   = it * 256 + tid;      // < 2048
        const int row = e >> 5;
        const int cw  = e & 31;
        uint2 hi, lo;
        split4(__ldg(xb + e), hi, lo);
        const uint32_t off = swz((uint32_t)row, (uint32_t)cw * 8u);
        *(uint2*)(smem + S1_AHI + off) = hi;
        *(uint2*)(smem + S1_ALO + off) = lo;
    }
    asm volatile("cp.async.wait_group 0;" ::: "memory");
    __syncthreads();

    // MMA: warp grid 2x4, warp tile 32(M) x 32(N)
    const int warpM = wid >> 2;
    const int warpN = wid & 3;
    const int q  = lane >> 3;
    const int lr = lane & 7;
    const int rowA  = lr + ((q & 1) << 3);
    const int cselA = q >> 1;
    uint32_t rowOffA[2];
    #pragma unroll
    for (int mt = 0; mt < 2; mt++)
        rowOffA[mt] = (uint32_t)(warpM * 32 + mt * 16 + rowA) * 256u;
    const int rowB  = lr + ((q >> 1) << 3);
    const int cselB = q & 1;
    uint32_t rowOffB[2];
    #pragma unroll
    for (int np = 0; np < 2; np++)
        rowOffB[np] = (uint32_t)(warpN * 32 + np * 16 + rowB) * 256u;

    float acc[2][4][4];
    #pragma unroll
    for (int mt = 0; mt < 2; mt++)
        #pragma unroll
        for (int nt = 0; nt < 4; nt++)
            #pragma unroll
            for (int e = 0; e < 4; e++) acc[mt][nt][e] = 0.f;

    const uint32_t slabsA[3] = { sbase + S1_AHI, sbase + S1_ALO, sbase + S1_AHI };
    const uint32_t slabsB[3] = { sbase + S1_BHI, sbase + S1_BHI, sbase + S1_BLO };
    #pragma unroll
    for (int p = 0; p < 3; p++) {
        const uint32_t sa = slabsA[p];
        const uint32_t sb = slabsB[p];
        #pragma unroll
        for (int kk = 0; kk < 8; kk++) {
            const uint32_t kxA = (uint32_t)(((kk << 1) + cselA) ^ lr) << 4;
            const uint32_t kxB = (uint32_t)(((kk << 1) + cselB) ^ lr) << 4;
            uint32_t af[2][4], bf[2][4];
            #pragma unroll
            for (int mt = 0; mt < 2; mt++) ldsm4(af[mt], sa + rowOffA[mt] + kxA);
            #pragma unroll
            for (int np = 0; np < 2; np++) ldsm4(bf[np], sb + rowOffB[np] + kxB);
            #pragma unroll
            for (int mt = 0; mt < 2; mt++)
                #pragma unroll
                for (int nt = 0; nt < 4; nt++) {
                    const int np = nt >> 1;
                    const int hb = (nt & 1) << 1;
                    mma16816(acc[mt][nt], af[mt], bf[np][hb], bf[np][hb + 1]);
                }
        }
    }

    if (chunk < 3) {
        // store C chunk
        float* cb = g_C + ((bn * 5 + chunk) * M_DIM) * F_DIM;
        #pragma unroll
        for (int mt = 0; mt < 2; mt++)
            #pragma unroll
            for (int half = 0; half < 2; half++) {
                const int m = warpM * 32 + mt * 16 + (lane >> 2) + half * 8;
                #pragma unroll
                for (int nt = 0; nt < 4; nt++) {
                    const int n = warpN * 32 + nt * 8 + (lane & 3) * 2;
                    *(float2*)(cb + m * 128 + n) =
                        make_float2(acc[mt][nt][half * 2], acc[mt][nt][half * 2 + 1]);
                }
            }
    } else {
        // colmean over the 64 rows -> g_means
        #pragma unroll
        for (int mt = 0; mt < 2; mt++)
            #pragma unroll
            for (int nt = 0; nt < 4; nt++) {
                const int n = warpN * 32 + nt * 8 + (lane & 3) * 2;
                atomicAdd(&cm[n],     acc[mt][nt][0] + acc[mt][nt][2]);
                atomicAdd(&cm[n + 1], acc[mt][nt][1] + acc[mt][nt][3]);
            }
        __syncthreads();
        if (tid < 128)
            g_means[(bn * 2 + (chunk - 3)) * F_DIM + tid] = cm[tid] * (1.0f / 64.0f);
    }
}

// ---------------------------------------------------------------------------
// Stage 2 (persistent): grid 304, B slabs + vectors loaded once, loop items.
// item -> (bn, i). h[j] = LN(P_i + Q_j + diag R_i) relu + diag bias_p; out = h.W2^T + b2.
// ---------------------------------------------------------------------------
#define S2_AHI 0
#define S2_ALO 16384
#define S2_BHI 32768
#define S2_BLO 65536
#define S2_VEC 98304
#define SMEM2_BYTES 102400

__global__ void __launch_bounds__(256, 2)
hoe_stage2p(const float* __restrict__ gamma,
            const float* __restrict__ beta,
            const float* __restrict__ bias_p,
            const float* __restrict__ b1,
            const float* __restrict__ b2,
            float* __restrict__ out) {
    extern __shared__ char smem[];
    float* Pv  = (float*)(smem + S2_VEC);
    float* Rv  = Pv + 128;
    float* gv  = Rv + 128;
    float* bv  = gv + 128;
    float* bpv = bv + 128;
    float* b2v = bpv + 128;

    const uint32_t sbase = cvta_smem(smem);
    const int tid  = threadIdx.x;
    const int lane = tid & 31;
    const int wid  = tid >> 5;

    // One-time: B slabs (W2 = mat 5) + vectors
    const unsigned char* bsrc = g_wsl + (5 * 2) * 32768;
    #pragma unroll
    for (int it = 0; it < 16; it++) {
        const int idx = it * 256 + tid;
        cp_async16(sbase + S2_BHI + idx * 16, bsrc + idx * 16);
    }
    asm volatile("cp.async.commit_group;" ::: "memory");
    if (tid < 128) {
        gv[tid]  = gamma[tid];
        bv[tid]  = beta[tid];
        bpv[tid] = bias_p[tid];
        b2v[tid] = b2[tid];
    }
    asm volatile("cp.async.wait_group 0;" ::: "memory");

    // MMA lane constants
    const int warpM = wid >> 2;
    const int warpN = wid & 3;
    const int q  = lane >> 3;
    const int lr = lane & 7;
    const int rowA  = lr + ((q & 1) << 3);
    const int cselA = q >> 1;
    uint32_t rowOffA[2];
    #pragma unroll
    for (int mt = 0; mt < 2; mt++)
        rowOffA[mt] = (uint32_t)(warpM * 32 + mt * 16 + rowA) * 256u;
    const int rowB  = lr + ((q >> 1) << 3);
    const int cselB = q & 1;
    uint32_t rowOffB[2];
    #pragma unroll
    for (int np = 0; np < 2; np++)
        rowOffB[np] = (uint32_t)(warpN * 32 + np * 16 + rowB) * 256u;

    const uint32_t slabsA[3] = { sbase + S2_AHI, sbase + S2_ALO, sbase + S2_AHI };
    const uint32_t slabsB[3] = { sbase + S2_BHI, sbase + S2_BHI, sbase + S2_BLO };
    const int f4 = lane * 4;

    for (int item = blockIdx.x; item < BN_TOT * M_DIM; item += gridDim.x) {
        const int bn = item >> 6;
        const int i  = item & 63;

        // Per-item vectors: P_i = C1[i] + mean-term + b1 ; R_i = C0[i] + mean-term
        if (tid < 128) {
            Pv[tid] = g_C[((bn * 5 + 1) * M_DIM + i) * F_DIM + tid]
                    + g_means[(bn * 2 + 1) * F_DIM + tid] + b1[tid];
            Rv[tid] = g_C[((bn * 5 + 0) * M_DIM + i) * F_DIM + tid]
                    + g_means[(bn * 2 + 0) * F_DIM + tid];
        }
        // Q rows prefetch (8 per warp)
        const float* Qg = g_C + ((bn * 5 + 2) * M_DIM) * F_DIM;
        float4 q4[8];
        #pragma unroll
        for (int r = 0; r < 8; r++)
            q4[r] = __ldg((const float4*)(Qg + (wid * 8 + r) * F_DIM + f4));

        __syncthreads();   // Pv/Rv visible; prev-iter MMA reads complete

        const float pv0 = Pv[f4], pv1 = Pv[f4 + 1], pv2 = Pv[f4 + 2], pv3 = Pv[f4 + 3];
        #pragma unroll
        for (int r = 0; r < 8; r++) {
            const int m = wid * 8 + r;            // j == m
            const bool diag = (m == i);
            float v0 = q4[r].x + pv0;
            float v1 = q4[r].y + pv1;
            float v2 = q4[r].z + pv2;
            float v3 = q4[r].w + pv3;
            if (diag) {
                v0 += Rv[f4 + 0]; v1 += Rv[f4 + 1];
                v2 += Rv[f4 + 2]; v3 += Rv[f4 + 3];
            }
            // fused sum / sumsq reduction (independent shfl chains)
            float s  = v0 + v1 + v2 + v3;
            float ss = v0 * v0 + v1 * v1 + v2 * v2 + v3 * v3;
            #pragma unroll
            for (int o = 16; o > 0; o >>= 1) {
                s  += __shfl_xor_sync(0xffffffffu, s,  o);
                ss += __shfl_xor_sync(0xffffffffu, ss, o);
            }
            const float mu   = s * (1.0f / F_DIM);
            const float var  = ss * (1.0f / F_DIM) - mu * mu;
            const float rstd = rsqrtf(var + EPS_LN);

            float h0 = fmaxf(fmaf((v0 - mu) * rstd, gv[f4 + 0], bv[f4 + 0]), 0.f);
            float h1 = fmaxf(fmaf((v1 - mu) * rstd, gv[f4 + 1], bv[f4 + 1]), 0.f);
            float h2 = fmaxf(fmaf((v2 - mu) * rstd, gv[f4 + 2], bv[f4 + 2]), 0.f);
            float h3 = fmaxf(fmaf((v3 - mu) * rstd, gv[f4 + 3], bv[f4 + 3]), 0.f);
            if (diag) {
                h0 += bpv[f4 + 0]; h1 += bpv[f4 + 1];
                h2 += bpv[f4 + 2]; h3 += bpv[f4 + 3];
            }
            uint2 hi, lo;
            split4(make_float4(h0, h1, h2, h3), hi, lo);
            const uint32_t off = swz((uint32_t)m, (uint32_t)lane * 8u);
            *(uint2*)(smem + S2_AHI + off) = hi;
            *(uint2*)(smem + S2_ALO + off) = lo;
        }
        __syncthreads();

        float acc[2][4][4];
        #pragma unroll
        for (int mt = 0; mt < 2; mt++)
            #pragma unroll
            for (int nt = 0; nt < 4; nt++)
                #pragma unroll
                for (int e = 0; e < 4; e++) acc[mt][nt][e] = 0.f;

        #pragma unroll
        for (int p = 0; p < 3; p++) {
            const uint32_t sa = slabsA[p];
            const uint32_t sb = slabsB[p];
            #pragma unroll
            for (int kk = 0; kk < 8; kk++) {
                const uint32_t kxA = (uint32_t)(((kk << 1) + cselA) ^ lr) << 4;
                const uint32_t kxB = (uint32_t)(((kk << 1) + cselB) ^ lr) << 4;
                uint32_t af[2][4], bf[2][4];
                #pragma unroll
                for (int mt = 0; mt < 2; mt++) ldsm4(af[mt], sa + rowOffA[mt] + kxA);
                #pragma unroll
                for (int np = 0; np < 2; np++) ldsm4(bf[np], sb + rowOffB[np] + kxB);
                #pragma unroll
                for (int mt = 0; mt < 2; mt++)
                    #pragma unroll
                    for (int nt = 0; nt < 4; nt++) {
                        const int np = nt >> 1;
                        const int hb = (nt & 1) << 1;
                        mma16816(acc[mt][nt], af[mt], bf[np][hb], bf[np][hb + 1]);
                    }
            }
        }

        // Epilogue
        float* oblk = out + (size_t)item * (M_DIM * D_DIM);
        #pragma unroll
        for (int mt = 0; mt < 2; mt++)
            #pragma unroll
            for (int half = 0; half < 2; half++) {
                const int m = warpM * 32 + mt * 16 + (lane >> 2) + half * 8;
                float* orow = oblk + (size_t)m * 128;
                #pragma unroll
                for (int nt = 0; nt < 4; nt++) {
                    const int n = warpN * 32 + nt * 8 + (lane & 3) * 2;
                    float2 v;
                    v.x = acc[mt][nt][half * 2 + 0] + b2v[n];
                    v.y = acc[mt][nt][half * 2 + 1] + b2v[n + 1];
                    *(float2*)(orow + n) = v;
                }
            }
    }
}

// ---------------------------------------------------------------------------
extern "C" void kernel_launch(void* const* d_in, const int* in_sizes, int n_in,
                              void* d_out, int out_size) {
    const float* x      = (const float*)d_in[0];
    const float* W1     = (const float*)d_in[1];
    const float* b1     = (const float*)d_in[2];
    const float* gamma  = (const float*)d_in[3];
    const float* beta   = (const float*)d_in[4];
    const float* bias_p = (const float*)d_in[5];
    const float* W2     = (const float*)d_in[6];
    const float* b2     = (const float*)d_in[7];
    float* out          = (float*)d_out;

    cudaFuncSetAttribute(hoe_stage1mm, cudaFuncAttributeMaxDynamicSharedMemorySize, SMEM1_BYTES);
    cudaFuncSetAttribute(hoe_stage2p,  cudaFuncAttributeMaxDynamicSharedMemorySize, SMEM2_BYTES);

    hoe_prep<<<96, 256>>>(W1, W2);
    hoe_stage1mm<<<dim3(BN_TOT, 5), 256, SMEM1_BYTES>>>(x);
    hoe_stage2p<<<304, 256, SMEM2_BYTES>>>(gamma, beta, bias_p, b1, b2, out);
}